// round 6
// baseline (speedup 1.0000x reference)
#include <cuda_runtime.h>
#include <cstdint>

// Problem constants
#define B_   16
#define N_   2048
#define F_   64
#define HD_  256
#define K_   128
#define G_   18
#define FUSE_ 274

// Scratch (allocation-free rule: __device__ globals)
__device__ float g_buf1[B_ * N_ * HD_];
__device__ float g_buf2[B_ * N_ * HD_];
__device__ float g_colsum[B_ * HD_];
__device__ float g_bufX[B_ * N_ * F_];
__device__ float g_bufW1[F_ * HD_];
__device__ float g_bufW2[HD_ * HD_];

// Epilogue modes
#define EPI_STORE_RND 0
#define EPI_LN_STORE  1
#define EPI_LN_COLSUM 2

// ---------------------------------------------------------------------------
__device__ __forceinline__ uint32_t smem_u32(const void* p) {
    uint32_t a;
    asm("{ .reg .u64 t; cvta.to.shared.u64 t, %1; cvt.u32.u64 %0, t; }"
        : "=r"(a) : "l"(p));
    return a;
}

__device__ __forceinline__ void cp16(uint32_t dst, const float* src) {
    asm volatile("cp.async.cg.shared.global [%0], [%1], 16;"
                 :: "r"(dst), "l"(src) : "memory");
}
#define CP_COMMIT() asm volatile("cp.async.commit_group;" ::: "memory")
#define CP_WAIT(n)  asm volatile("cp.async.wait_group %0;" :: "n"(n) : "memory")

__device__ __forceinline__ float rna_tf32(float f) {
    uint32_t u;
    asm("cvt.rna.tf32.f32 %0, %1;" : "=r"(u) : "f"(f));
    return __uint_as_float(u);
}

__device__ __forceinline__ void mma8(float* c, const uint32_t* a, const uint32_t* b) {
    asm volatile(
        "mma.sync.aligned.m16n8k8.row.col.f32.tf32.tf32.f32 "
        "{%0,%1,%2,%3}, {%4,%5,%6,%7}, {%8,%9}, {%0,%1,%2,%3};"
        : "+f"(c[0]), "+f"(c[1]), "+f"(c[2]), "+f"(c[3])
        : "r"(a[0]), "r"(a[1]), "r"(a[2]), "r"(a[3]), "r"(b[0]), "r"(b[1]));
}

// ---------------------------------------------------------------------------
__global__ __launch_bounds__(256)
void round_tf32_kernel(const float* __restrict__ in, float* __restrict__ out, int n4) {
    int i = blockIdx.x * blockDim.x + threadIdx.x;
    if (i < n4) {
        float4 v = reinterpret_cast<const float4*>(in)[i];
        v.x = rna_tf32(v.x); v.y = rna_tf32(v.y);
        v.z = rna_tf32(v.z); v.w = rna_tf32(v.w);
        reinterpret_cast<float4*>(out)[i] = v;
    }
}

// ---------------------------------------------------------------------------
// TF32 mma.sync GEMM with fused epilogues: C[bz] = A[bz] @ Bm[bz]
// BM=128, BN/warp-grid/epilogue/stage-count/min-blocks/frag-DB templated.
// 256 threads = 8 warps. No cvt in hot loop (A truncated, B pre-rounded).
// ---------------------------------------------------------------------------
template <int BN, int WROWS, int WCOLS, int EPI, int S, int MINB, bool DB>
__global__ __launch_bounds__(256, MINB)
void tf32_mma_gemm(const float* __restrict__ A, const float* __restrict__ Bm,
                   float* __restrict__ C, int Kd, int Ncols,
                   long long sA, long long sB, long long sC,
                   const float* __restrict__ bias,
                   const float* __restrict__ gamma,
                   const float* __restrict__ beta,
                   float* __restrict__ colsum) {
    constexpr int BM = 128, BK = 32;
    constexpr int WM = BM / WROWS, WN = BN / WCOLS;
    constexpr int MF = WM / 16, NF = WN / 8;
    constexpr int AP = 36;          // A smem pitch: conflict-free frag reads
    constexpr int BP = BN + 8;      // B smem pitch
    constexpr int AS_F = BM * AP;
    constexpr int BS_F = BK * BP;
    constexpr int ST_F = AS_F + BS_F;
    constexpr int EP = 260;         // LN epilogue tile pitch (BN=256 only)

    extern __shared__ float smem[];
    const uint32_t sbase = smem_u32(smem);

    const int tid  = threadIdx.x;
    const int lane = tid & 31, wid = tid >> 5;
    const int wm = (wid / WCOLS) * WM;
    const int wn = (wid % WCOLS) * WN;

    const long long bz = blockIdx.z;
    const float* Ab = A + bz * sA + (long long)blockIdx.y * BM * Kd;
    const float* Bb = Bm + bz * sB + blockIdx.x * BN;
    float*       Cb = (EPI == EPI_LN_COLSUM) ? nullptr
                      : C + bz * sC + (long long)blockIdx.y * BM * Ncols
                          + blockIdx.x * BN;

    float acc[MF][NF][4];
#pragma unroll
    for (int i = 0; i < MF; i++)
#pragma unroll
        for (int j = 0; j < NF; j++)
#pragma unroll
            for (int r = 0; r < 4; r++) acc[i][j][r] = 0.f;

    const int nch = Kd >> 5;

    auto load_stage = [&](int s, int kc) {
        const float* Ak = Ab + kc * BK;
#pragma unroll
        for (int i = 0; i < 4; i++) {
            int idx = tid + i * 256;
            int r = idx >> 3, c4 = idx & 7;
            uint32_t dst = sbase + (uint32_t)(s * ST_F + r * AP + c4 * 4) * 4u;
            cp16(dst, Ak + (long long)r * Kd + c4 * 4);
        }
        const float* Bk = Bb + (long long)(kc * BK) * Ncols;
        constexpr int BI = (BN * BK) / (4 * 256);
        constexpr int C4 = BN / 4;
#pragma unroll
        for (int i = 0; i < BI; i++) {
            int idx = tid + i * 256;
            int r = idx / C4, c4 = idx % C4;
            uint32_t dst = sbase +
                (uint32_t)(s * ST_F + AS_F + r * BP + c4 * 4) * 4u;
            cp16(dst, Bk + (long long)r * Ncols + c4 * 4);
        }
    };

    auto compute_stage = [&](int s) {
        const uint32_t* As = reinterpret_cast<const uint32_t*>(smem + s * ST_F);
        const uint32_t* Bs = reinterpret_cast<const uint32_t*>(smem + s * ST_F + AS_F);

        auto load_frags = [&](uint32_t af[MF][4], uint32_t bf[NF][2], int k0) {
#pragma unroll
            for (int mf = 0; mf < MF; mf++) {
                int m = wm + mf * 16 + (lane >> 2);
                int k = k0 + (lane & 3);
                af[mf][0] = As[m * AP + k];
                af[mf][1] = As[(m + 8) * AP + k];
                af[mf][2] = As[m * AP + k + 4];
                af[mf][3] = As[(m + 8) * AP + k + 4];
            }
#pragma unroll
            for (int nf = 0; nf < NF; nf++) {
                int n = wn + nf * 8 + (lane >> 2);
                int k = k0 + (lane & 3);
                bf[nf][0] = Bs[k * BP + n];
                bf[nf][1] = Bs[(k + 4) * BP + n];
            }
        };

        if (DB) {
            uint32_t af[2][MF][4], bf[2][NF][2];
            load_frags(af[0], bf[0], 0);
#pragma unroll
            for (int kk = 0; kk < 4; kk++) {
                if (kk < 3) load_frags(af[(kk + 1) & 1], bf[(kk + 1) & 1], (kk + 1) * 8);
#pragma unroll
                for (int mf = 0; mf < MF; mf++)
#pragma unroll
                    for (int nf = 0; nf < NF; nf++)
                        mma8(acc[mf][nf], af[kk & 1][mf], bf[kk & 1][nf]);
            }
        } else {
#pragma unroll
            for (int kk = 0; kk < 4; kk++) {
                uint32_t af[MF][4], bf[NF][2];
                load_frags(af, bf, kk * 8);
#pragma unroll
                for (int mf = 0; mf < MF; mf++)
#pragma unroll
                    for (int nf = 0; nf < NF; nf++)
                        mma8(acc[mf][nf], af[mf], bf[nf]);
            }
        }
    };

#pragma unroll
    for (int s = 0; s < S - 1; s++) {
        if (s < nch) load_stage(s, s);
        CP_COMMIT();
    }
    for (int kc = 0; kc < nch; kc++) {
        CP_WAIT(S - 2);
        __syncthreads();
        if (kc + S - 1 < nch) load_stage((kc + S - 1) % S, kc + S - 1);
        CP_COMMIT();
        compute_stage(kc % S);
        __syncthreads();
    }

    if (EPI == EPI_STORE_RND) {
#pragma unroll
        for (int mf = 0; mf < MF; mf++) {
#pragma unroll
            for (int nf = 0; nf < NF; nf++) {
                int row = wm + mf * 16 + (lane >> 2);
                int col = wn + nf * 8 + (lane & 3) * 2;
                float2 v0 = make_float2(rna_tf32(acc[mf][nf][0]),
                                        rna_tf32(acc[mf][nf][1]));
                float2 v1 = make_float2(rna_tf32(acc[mf][nf][2]),
                                        rna_tf32(acc[mf][nf][3]));
                *reinterpret_cast<float2*>(Cb + (long long)row * Ncols + col) = v0;
                *reinterpret_cast<float2*>(Cb + (long long)(row + 8) * Ncols + col) = v1;
            }
        }
        return;
    }

    // ---- Fused bias + LayerNorm + ReLU epilogue (BN == HD_ == 256) ----
    __syncthreads();
#pragma unroll
    for (int mf = 0; mf < MF; mf++) {
#pragma unroll
        for (int nf = 0; nf < NF; nf++) {
            int row = wm + mf * 16 + (lane >> 2);
            int col = wn + nf * 8 + (lane & 3) * 2;
            smem[row * EP + col]     = acc[mf][nf][0];
            smem[row * EP + col + 1] = acc[mf][nf][1];
            smem[(row + 8) * EP + col]     = acc[mf][nf][2];
            smem[(row + 8) * EP + col + 1] = acc[mf][nf][3];
        }
    }
    __syncthreads();

    // Per-lane LN params (cols lane*8..lane*8+7), loaded once
    float rb[8], rg[8], rt[8];
#pragma unroll
    for (int j = 0; j < 8; j++) {
        rb[j] = __ldg(&bias[lane * 8 + j]);
        rg[j] = __ldg(&gamma[lane * 8 + j]);
        rt[j] = __ldg(&beta[lane * 8 + j]);
    }

    const float inv = 1.f / (float)HD_;
#pragma unroll 1
    for (int rr = 0; rr < 16; rr++) {
        const int r = wid * 16 + rr;
        float x[8];
        float4 v0 = *reinterpret_cast<float4*>(&smem[r * EP + lane * 8]);
        float4 v1 = *reinterpret_cast<float4*>(&smem[r * EP + lane * 8 + 4]);
        x[0] = v0.x; x[1] = v0.y; x[2] = v0.z; x[3] = v0.w;
        x[4] = v1.x; x[5] = v1.y; x[6] = v1.z; x[7] = v1.w;
        float s = 0.f, s2 = 0.f;
#pragma unroll
        for (int j = 0; j < 8; j++) {
            x[j] += rb[j];
            s += x[j]; s2 += x[j] * x[j];
        }
#pragma unroll
        for (int o = 16; o; o >>= 1) {
            s  += __shfl_xor_sync(0xFFFFFFFFu, s, o);
            s2 += __shfl_xor_sync(0xFFFFFFFFu, s2, o);
        }
        float mu = s * inv;
        float rstd = rsqrtf(s2 * inv - mu * mu + 1e-5f);
        float y[8];
#pragma unroll
        for (int j = 0; j < 8; j++) {
            float v = (x[j] - mu) * rstd * rg[j] + rt[j];
            y[j] = fmaxf(v, 0.f);
        }
        if (EPI == EPI_LN_STORE) {
#pragma unroll
            for (int j = 0; j < 8; j++) y[j] = rna_tf32(y[j]);
            float* crow = C + (long long)blockIdx.y * BM * Ncols
                            + (long long)r * Ncols + lane * 8;
            *reinterpret_cast<float4*>(crow)     = make_float4(y[0], y[1], y[2], y[3]);
            *reinterpret_cast<float4*>(crow + 4) = make_float4(y[4], y[5], y[6], y[7]);
        } else {
            *reinterpret_cast<float4*>(&smem[r * EP + lane * 8]) =
                make_float4(y[0], y[1], y[2], y[3]);
            *reinterpret_cast<float4*>(&smem[r * EP + lane * 8 + 4]) =
                make_float4(y[4], y[5], y[6], y[7]);
        }
    }

    if (EPI == EPI_LN_COLSUM) {
        __syncthreads();
        float s = 0.f;
#pragma unroll 8
        for (int r = 0; r < BM; r++) s += smem[r * EP + tid];
        const int b = (int)(blockIdx.y >> 4);
        atomicAdd(&colsum[b * HD_ + tid], s);
    }
}

// ---------------------------------------------------------------------------
__global__ __launch_bounds__(256)
void head_kernel(const float* __restrict__ colsum, const float* __restrict__ gvec,
                 const float* __restrict__ Ws, const float* __restrict__ bs,
                 const float* __restrict__ Wa, const float* __restrict__ ba,
                 float* __restrict__ out) {
    int b = blockIdx.x, t = threadIdx.x;
    __shared__ float fused[FUSE_];
    fused[t] = colsum[b * HD_ + t] * (1.f / (float)N_);
    if (t < G_) fused[HD_ + t] = gvec[b * G_ + t];
    __syncthreads();

    if (t < K_) {
        float acc = ba[t];
#pragma unroll 4
        for (int i = 0; i < FUSE_; i++) acc += fused[i] * Wa[i * K_ + t];
        out[B_ + b * K_ + t] = acc;
    } else if (t == K_) {
        float acc = bs[0];
        for (int i = 0; i < FUSE_; i++) acc += fused[i] * Ws[i];
        out[b] = acc;
    }
}

// ---------------------------------------------------------------------------
extern "C" void kernel_launch(void* const* d_in, const int* in_sizes, int n_in,
                              void* d_out, int out_size) {
    const float* A_hat = (const float*)d_in[0];
    const float* X     = (const float*)d_in[1];
    const float* gvec  = (const float*)d_in[2];
    const float* W1    = (const float*)d_in[3];
    const float* b1    = (const float*)d_in[4];
    const float* g1    = (const float*)d_in[5];
    const float* be1   = (const float*)d_in[6];
    const float* W2    = (const float*)d_in[7];
    const float* b2    = (const float*)d_in[8];
    const float* g2    = (const float*)d_in[9];
    const float* be2   = (const float*)d_in[10];
    const float* Ws    = (const float*)d_in[11];
    const float* bs    = (const float*)d_in[12];
    const float* Wa    = (const float*)d_in[13];
    const float* ba    = (const float*)d_in[14];
    float* out = (float*)d_out;

    float *buf1, *buf2, *csum, *bX, *bW1, *bW2;
    cudaGetSymbolAddress((void**)&buf1, g_buf1);
    cudaGetSymbolAddress((void**)&buf2, g_buf2);
    cudaGetSymbolAddress((void**)&csum, g_colsum);
    cudaGetSymbolAddress((void**)&bX,  g_bufX);
    cudaGetSymbolAddress((void**)&bW1, g_bufW1);
    cudaGetSymbolAddress((void**)&bW2, g_bufW2);

    // K1: BN=64, S=4, DB, 2 CTAs/SM.  ST_F = 128*36 + 32*72 = 6912 fl
    constexpr int SMEM_K1 = 4 * 6912 * 4;                   // 110592
    // K3: BN=128, S=2, 2 CTAs/SM.     ST_F = 128*36 + 32*136 = 8960 fl
    constexpr int SMEM_K3 = 2 * 8960 * 4;                   // 71680
    // K2/K4: BN=256, S=2, LN tile 128*260 dominates
    constexpr int SMEM_LN = 128 * 260 * 4;                  // 133120

    using GemmK1 = void(*)(const float*, const float*, float*, int, int,
                           long long, long long, long long,
                           const float*, const float*, const float*, float*);
    GemmK1 k1 = tf32_mma_gemm<64, 4, 2, EPI_STORE_RND, 4, 1, true>;
    GemmK1 k3 = tf32_mma_gemm<128, 4, 2, EPI_STORE_RND, 2, 2, false>;
    GemmK1 k2 = tf32_mma_gemm<256, 2, 4, EPI_LN_STORE, 2, 1, false>;
    GemmK1 k4 = tf32_mma_gemm<256, 2, 4, EPI_LN_COLSUM, 2, 1, false>;

    cudaFuncSetAttribute((const void*)k1, cudaFuncAttributeMaxDynamicSharedMemorySize, SMEM_K1);
    cudaFuncSetAttribute((const void*)k3, cudaFuncAttributeMaxDynamicSharedMemorySize, SMEM_K3);
    cudaFuncSetAttribute((const void*)k2, cudaFuncAttributeMaxDynamicSharedMemorySize, SMEM_LN);
    cudaFuncSetAttribute((const void*)k4, cudaFuncAttributeMaxDynamicSharedMemorySize, SMEM_LN);

    round_tf32_kernel<<<(B_ * N_ * F_ / 4 + 255) / 256, 256>>>(X,  bX,  B_ * N_ * F_ / 4);
    round_tf32_kernel<<<(F_ * HD_ / 4 + 255) / 256, 256>>>(W1, bW1, F_ * HD_ / 4);
    round_tf32_kernel<<<(HD_ * HD_ / 4 + 255) / 256, 256>>>(W2, bW2, HD_ * HD_ / 4);
    cudaMemsetAsync(csum, 0, B_ * HD_ * sizeof(float));

    // K1: T1 = A_hat @ X  -> buf1 (rounded)
    k1<<<dim3(1, 16, 16), 256, SMEM_K1>>>(
        A_hat, bX, buf1, N_, F_,
        (long long)N_ * N_, (long long)N_ * F_, (long long)N_ * F_,
        nullptr, nullptr, nullptr, nullptr);
    // K2: H1 = relu(LN(T1@W1 + b1)) -> buf2 (rounded)
    k2<<<dim3(1, 256, 1), 256, SMEM_LN>>>(
        buf1, bW1, buf2, F_, HD_, 0, 0, 0, b1, g1, be1, nullptr);
    // K3: T2 = A_hat @ H1 -> buf1 (rounded)
    k3<<<dim3(2, 16, 16), 256, SMEM_K3>>>(
        A_hat, buf2, buf1, N_, HD_,
        (long long)N_ * N_, (long long)N_ * HD_, (long long)N_ * HD_,
        nullptr, nullptr, nullptr, nullptr);
    // K4: colsum += colsums(relu(LN(T2@W2 + b2)))
    k4<<<dim3(1, 256, 1), 256, SMEM_LN>>>(
        buf1, bW2, nullptr, HD_, HD_, 0, 0, 0, b2, g2, be2, csum);
    // K5: mean + concat + heads -> out
    head_kernel<<<B_, 256>>>(csum, gvec, Ws, bs, Wa, ba, out);
}